// round 11
// baseline (speedup 1.0000x reference)
#include <cuda_runtime.h>
#include <cuda_bf16.h>

#define VOCAB    128000
#define HISTLEN  2048
#define TOPK     15
#define NBLK     125           // 125 blocks * 256 thr * 4 elem == 128000 exactly
#define NTHR     256
#define NWARP    (NTHR / 32)   // 8
#define NEG_KEY  0ull

// ---------------- device scratch (allocations forbidden) ----------------
__device__ unsigned           g_bitmap[VOCAB / 32];     // penalized membership
__device__ unsigned long long g_btop[NBLK * TOPK];      // per-block top keys
__device__ float              g_lmax, g_pivot, g_S;
__device__ unsigned long long g_amax;
__device__ unsigned           g_ctrB, g_ctrD;           // last-block counters

// monotone map float -> unsigned (total order; NaN above +inf) + inverse
__device__ __forceinline__ unsigned ordered(float f) {
    unsigned u = __float_as_uint(f);
    return u ^ ((u & 0x80000000u) ? 0xFFFFFFFFu : 0x80000000u);
}
__device__ __forceinline__ float unordered(unsigned x) {
    unsigned u = (x & 0x80000000u) ? (x ^ 0x80000000u) : (x ^ 0xFFFFFFFFu);
    return __uint_as_float(u);
}
__device__ __forceinline__ unsigned long long make_key(float v, int i) {
    return ((unsigned long long)ordered(v) << 32)
         | (unsigned long long)(0xFFFFFFFFu - (unsigned)i);
}
__device__ __forceinline__ unsigned long long warp_max(unsigned long long k) {
    #pragma unroll
    for (int off = 16; off; off >>= 1) {
        unsigned long long o = __shfl_xor_sync(0xffffffffu, k, off);
        if (o > k) k = o;
    }
    return k;
}

// penalty applied to a float4 of original logits; one bitmap word covers all
// 4 lanes (base%4==0 -> same 32-bit word). _rn ops match f32 reference exactly.
__device__ __forceinline__ float4 plog4(float4 r, int base) {
    unsigned w = g_bitmap[base >> 5];
    unsigned sh = (unsigned)(base & 31);
    if ((w >> (sh + 0)) & 1u) r.x = (r.x < 0.f) ? __fmul_rn(r.x, 1.35f) : __fdiv_rn(r.x, 1.35f);
    if ((w >> (sh + 1)) & 1u) r.y = (r.y < 0.f) ? __fmul_rn(r.y, 1.35f) : __fdiv_rn(r.y, 1.35f);
    if ((w >> (sh + 2)) & 1u) r.z = (r.z < 0.f) ? __fmul_rn(r.z, 1.35f) : __fdiv_rn(r.z, 1.35f);
    if ((w >> (sh + 3)) & 1u) r.w = (r.w < 0.f) ? __fmul_rn(r.w, 1.35f) : __fdiv_rn(r.w, 1.35f);
    return r;
}

// KA (1 block): reset state, build membership bitmap, copy y (AS FLOATS)
__global__ void kA_prep(const int* __restrict__ y, float* __restrict__ out,
                        int out_size) {
    int tid = threadIdx.x;
    for (int j = tid; j < VOCAB / 32; j += NTHR) g_bitmap[j] = 0u;
    if (tid == 0) { g_amax = 0ull; g_ctrB = 0u; g_ctrD = 0u; }
    __syncthreads();
    const bool full = (out_size >= HISTLEN + 2);
    for (int t = tid; t < HISTLEN; t += NTHR) {
        int p = y[t];
        if (full) out[1 + t] = (float)p;          // exact: p < 2^24
        p = min(max(p, 0), VOCAB - 1);            // clamp: OOB impossible
        atomicOr(&g_bitmap[p >> 5], 1u << (p & 31));
    }
}

// KBC (125 blocks): vectorized exact per-block top-15; LAST block merges all
// 1875 block-top keys -> lmax / pivot / softmax denominator S.
__global__ void __launch_bounds__(NTHR, 1)
kBC_top(const float* __restrict__ logits) {
    __shared__ unsigned long long swtop[NWARP * TOPK];   // 120 warp candidates
    __shared__ unsigned long long sall[NBLK * TOPK];     // 1875 (last block)
    __shared__ int s_last;
    int tid = threadIdx.x, lane = tid & 31, w = tid >> 5;

    int base = (blockIdx.x * NTHR + tid) * 4;
    float4 r = plog4(*(const float4*)(logits + base), base);
    unsigned long long k0 = make_key(r.x, base + 0);
    unsigned long long k1 = make_key(r.y, base + 1);
    unsigned long long k2 = make_key(r.z, base + 2);
    unsigned long long k3 = make_key(r.w, base + 3);

    // warp top-15 over 128 unique keys: repeated (warp max, owner pops)
    #pragma unroll
    for (int k = 0; k < TOPK; k++) {
        unsigned long long lm = k0;
        if (k1 > lm) lm = k1;
        if (k2 > lm) lm = k2;
        if (k3 > lm) lm = k3;
        unsigned long long m = warp_max(lm);
        if (lane == 0) swtop[w * TOPK + k] = m;
        if (k0 == m) k0 = NEG_KEY;                // unique keys: exactly one pops
        else if (k1 == m) k1 = NEG_KEY;
        else if (k2 == m) k2 = NEG_KEY;
        else if (k3 == m) k3 = NEG_KEY;
    }
    __syncthreads();
    if (w == 0) {                                 // merge 120 -> block top-15
        for (int k = 0; k < TOPK; k++) {
            unsigned long long lm = NEG_KEY; int lp = 0;
            for (int j = lane; j < NWARP * TOPK; j += 32) {
                unsigned long long x = swtop[j];
                if (x > lm) { lm = x; lp = j; }
            }
            unsigned long long m = warp_max(lm);
            if (lm == m && lm != NEG_KEY) swtop[lp] = NEG_KEY;
            __syncwarp();
            if (lane == 0) g_btop[blockIdx.x * TOPK + k] = m;  // stores by tid 0
        }
    }
    __syncthreads();
    if (tid == 0) {
        __threadfence();                          // publish tid0's g_btop stores
        s_last = (atomicAdd(&g_ctrB, 1u) == gridDim.x - 1);
    }
    __syncthreads();
    if (!s_last) return;
    __threadfence();                              // acquire all blocks' stores
    for (int j = tid; j < NBLK * TOPK; j += NTHR) sall[j] = g_btop[j];
    __syncthreads();
    if (w == 0) {
        float top[TOPK];
        for (int k = 0; k < TOPK; k++) {
            unsigned long long lm = NEG_KEY; int lp = 0;
            for (int j = lane; j < NBLK * TOPK; j += 32) {
                unsigned long long x = sall[j];
                if (x > lm) { lm = x; lp = j; }
            }
            unsigned long long m = warp_max(lm);
            if (lm == m && lm != NEG_KEY) sall[lp] = NEG_KEY;
            __syncwarp();
            top[k] = unordered((unsigned)(m >> 32));
        }
        if (lane == 0) {
            float lmax = top[0];
            float S = 0.0f;                       // kept set IS these 15 values
            for (int k = 0; k < TOPK; k++) S += expf(top[k] - lmax);
            g_lmax = lmax; g_pivot = top[TOPK - 1]; g_S = S;
        }
    }
}

// KDE (125 blocks): vectorized argmax(probs/noise); LAST block writes sample.
// kept: (exp(l-lmax)/S)/noise ; masked: 0/noise (exact +-0 / NaN like ref).
// +-0 unify to ONE key (first-index ties, IEEE +0==-0 under jnp.argmax);
// NaN keys order above everything (NaN propagation).
__global__ void __launch_bounds__(NTHR, 1)
kDE_argmax(const float* __restrict__ logits, const float* __restrict__ noise,
           float* __restrict__ out, int out_size) {
    __shared__ unsigned long long red[NWARP];
    __shared__ int s_last;
    int tid = threadIdx.x, lane = tid & 31, w = tid >> 5;
    const float piv = g_pivot, lmax = g_lmax, S = g_S;

    int base = (blockIdx.x * NTHR + tid) * 4;
    float4 l = plog4(*(const float4*)(logits + base), base);
    float4 nz = *(const float4*)(noise + base);

    auto key_of = [&](float lv, float nv, int i) -> unsigned long long {
        float v = (lv >= piv) ? __fdiv_rn(__fdiv_rn(expf(lv - lmax), S), nv)
                              : __fdiv_rn(0.0f, nv);
        unsigned ov = (v == 0.0f) ? 0x80000000u : ordered(v);
        return ((unsigned long long)ov << 32)
             | (unsigned long long)(0xFFFFFFFFu - (unsigned)i);
    };
    unsigned long long b = key_of(l.x, nz.x, base + 0);
    unsigned long long t1 = key_of(l.y, nz.y, base + 1); if (t1 > b) b = t1;
    unsigned long long t2 = key_of(l.z, nz.z, base + 2); if (t2 > b) b = t2;
    unsigned long long t3 = key_of(l.w, nz.w, base + 3); if (t3 > b) b = t3;

    b = warp_max(b);
    if (lane == 0) red[w] = b;
    __syncthreads();
    if (w == 0) {
        unsigned long long m = (lane < NWARP) ? red[lane] : NEG_KEY;
        m = warp_max(m);
        if (lane == 0) atomicMax(&g_amax, m);
    }
    __syncthreads();
    if (tid == 0) {
        __threadfence();
        s_last = (atomicAdd(&g_ctrD, 1u) == gridDim.x - 1);
    }
    __syncthreads();
    if (!s_last) return;
    if (tid == 0) {
        unsigned long long m = atomicAdd(&g_amax, 0ull);   // coherent L2 read
        float fidx = (float)(int)(0xFFFFFFFFu - (unsigned)(m & 0xFFFFFFFFull));
        out[0] = fidx;                                     // samples
        if (out_size >= HISTLEN + 2) out[1 + HISTLEN] = fidx;  // y_new tail
        for (int j = HISTLEN + 2; j < out_size; j++) out[j] = fidx;
    }
}

extern "C" void kernel_launch(void* const* d_in, const int* in_sizes, int n_in,
                              void* d_out, int out_size) {
    // y = the size-2048 tensor; among the remaining two (metadata order),
    // logits precedes noise (validated in rounds 9-10).
    int iy = 1;
    for (int i = 0; i < n_in; i++) if (in_sizes[i] == HISTLEN) { iy = i; break; }
    int fl[2]; int nf = 0;
    for (int i = 0; i < n_in && nf < 2; i++) if (i != iy) fl[nf++] = i;

    const float* logits = (const float*)d_in[fl[0]];
    const float* noise  = (const float*)d_in[fl[1]];
    const int*   y      = (const int*)d_in[iy];
    float* out = (float*)d_out;

    kA_prep   <<<1,    NTHR>>>(y, out, out_size);
    kBC_top   <<<NBLK, NTHR>>>(logits);
    kDE_argmax<<<NBLK, NTHR>>>(logits, noise, out, out_size);
}

// round 12
// speedup vs baseline: 1.0465x; 1.0465x over previous
#include <cuda_runtime.h>
#include <cuda_bf16.h>

#define VOCAB    128000
#define HISTLEN  2048
#define TOPK     15
#define NBLK     125           // 125 blocks * 256 thr * 4 elem == 128000 exactly
#define NTHR     256
#define NWARP    (NTHR / 32)   // 8
#define NEG_KEY  0ull

// -------- device scratch (allocations forbidden; ALL self-cleaning) --------
// Invariant: at every kernel_launch entry, g_bitmap == 0, g_ctrB == g_ctrD == 0,
// g_amax == 0. Static zero-init establishes it; each call restores it at exit.
__device__ unsigned           g_bitmap[VOCAB / 32];
__device__ unsigned long long g_btop[NBLK * TOPK];
__device__ float              g_lmax, g_pivot, g_S;
__device__ unsigned long long g_amax;
__device__ unsigned           g_ctrB, g_ctrD;

// monotone map float -> unsigned (total order; NaN above +inf) + inverse
__device__ __forceinline__ unsigned ordered(float f) {
    unsigned u = __float_as_uint(f);
    return u ^ ((u & 0x80000000u) ? 0xFFFFFFFFu : 0x80000000u);
}
__device__ __forceinline__ float unordered(unsigned x) {
    unsigned u = (x & 0x80000000u) ? (x ^ 0x80000000u) : (x ^ 0xFFFFFFFFu);
    return __uint_as_float(u);
}
__device__ __forceinline__ unsigned long long make_key(float v, int i) {
    return ((unsigned long long)ordered(v) << 32)
         | (unsigned long long)(0xFFFFFFFFu - (unsigned)i);
}
__device__ __forceinline__ unsigned long long warp_max(unsigned long long k) {
    #pragma unroll
    for (int off = 16; off; off >>= 1) {
        unsigned long long o = __shfl_xor_sync(0xffffffffu, k, off);
        if (o > k) k = o;
    }
    return k;
}

// penalty on a float4 of original logits; one bitmap word covers all 4 lanes
// (base%4==0). _rn ops are bit-identical to the f32 reference.
__device__ __forceinline__ float4 plog4(float4 r, int base) {
    unsigned w = g_bitmap[base >> 5];
    unsigned sh = (unsigned)(base & 31);
    if ((w >> (sh + 0)) & 1u) r.x = (r.x < 0.f) ? __fmul_rn(r.x, 1.35f) : __fdiv_rn(r.x, 1.35f);
    if ((w >> (sh + 1)) & 1u) r.y = (r.y < 0.f) ? __fmul_rn(r.y, 1.35f) : __fdiv_rn(r.y, 1.35f);
    if ((w >> (sh + 2)) & 1u) r.z = (r.z < 0.f) ? __fmul_rn(r.z, 1.35f) : __fdiv_rn(r.z, 1.35f);
    if ((w >> (sh + 3)) & 1u) r.w = (r.w < 0.f) ? __fmul_rn(r.w, 1.35f) : __fdiv_rn(r.w, 1.35f);
    return r;
}

// extract the current max of sh-array slice [lo,hi) (warp-collective), pop it
__device__ __forceinline__ unsigned long long
slice_extract(volatile unsigned long long* arr, int lo, int hi, int lane) {
    unsigned long long lm = NEG_KEY; int lp = lo;
    for (int j = lo + lane; j < hi; j += 32) {
        unsigned long long x = arr[j];
        if (x > lm) { lm = x; lp = j; }
    }
    unsigned long long m = warp_max(lm);
    if (lm == m && lm != NEG_KEY) arr[lp] = NEG_KEY;   // unique keys: one owner
    __syncwarp();
    return m;
}

// KA (8 blocks x 256 = 2048): scatter bitmap + copy y (AS FLOATS).
// Bitmap is already zero on entry (self-cleaning invariant).
__global__ void kA_prep(const int* __restrict__ y, float* __restrict__ out,
                        int out_size) {
    int t = blockIdx.x * NTHR + threadIdx.x;      // exactly HISTLEN threads
    int p = y[t];
    if (out_size >= HISTLEN + 2) out[1 + t] = (float)p;   // exact: p < 2^24
    p = min(max(p, 0), VOCAB - 1);                // clamp: OOB impossible
    atomicOr(&g_bitmap[p >> 5], 1u << (p & 31));
}

// KBC (125 blocks): vectorized exact per-block top-15; LAST block merges all
// 1875 block-top keys hierarchically (8 warps) -> lmax / pivot / S.
__global__ void __launch_bounds__(NTHR, 1)
kBC_top(const float* __restrict__ logits) {
    __shared__ unsigned long long swtop[NWARP * TOPK];   // 120
    __shared__ unsigned long long sall[NBLK * TOPK];     // 1875 (last block)
    __shared__ int s_last;
    int tid = threadIdx.x, lane = tid & 31, w = tid >> 5;

    int base = (blockIdx.x * NTHR + tid) * 4;
    float4 r = plog4(*(const float4*)(logits + base), base);
    unsigned long long k0 = make_key(r.x, base + 0);
    unsigned long long k1 = make_key(r.y, base + 1);
    unsigned long long k2 = make_key(r.z, base + 2);
    unsigned long long k3 = make_key(r.w, base + 3);

    #pragma unroll
    for (int k = 0; k < TOPK; k++) {              // warp top-15 of 128 keys
        unsigned long long lm = k0;
        if (k1 > lm) lm = k1;
        if (k2 > lm) lm = k2;
        if (k3 > lm) lm = k3;
        unsigned long long m = warp_max(lm);
        if (lane == 0) swtop[w * TOPK + k] = m;
        if (k0 == m) k0 = NEG_KEY;
        else if (k1 == m) k1 = NEG_KEY;
        else if (k2 == m) k2 = NEG_KEY;
        else if (k3 == m) k3 = NEG_KEY;
    }
    __syncthreads();
    if (w == 0) {                                 // 120 -> block top-15
        for (int k = 0; k < TOPK; k++) {
            unsigned long long m = slice_extract(swtop, 0, NWARP * TOPK, lane);
            if (lane == 0) g_btop[blockIdx.x * TOPK + k] = m;
        }
    }
    __syncthreads();
    if (tid == 0) {
        __threadfence();
        unsigned c = atomicAdd(&g_ctrB, 1u);
        s_last = (c == gridDim.x - 1);
        if (s_last) g_ctrB = 0u;                  // self-clean for next call
    }
    __syncthreads();
    if (!s_last) return;
    __threadfence();                              // acquire all blocks' g_btop
    for (int j = tid; j < NBLK * TOPK; j += NTHR) sall[j] = g_btop[j];
    __syncthreads();
    // level 1: 8 warps, each extracts top-15 of its ~235-key slice
    {
        int lo = w * 235, hi = min(lo + 235, NBLK * TOPK);
        for (int k = 0; k < TOPK; k++) {
            unsigned long long m = slice_extract(sall, lo, hi, lane);
            if (lane == 0) swtop[w * TOPK + k] = m;
        }
    }
    __syncthreads();
    // level 2: warp 0 extracts top-15 of the 120 survivors
    if (w == 0) {
        float top[TOPK];
        for (int k = 0; k < TOPK; k++) {
            unsigned long long m = slice_extract(swtop, 0, NWARP * TOPK, lane);
            top[k] = unordered((unsigned)(m >> 32));
        }
        if (lane == 0) {
            float lmax = top[0];
            float S = 0.0f;                       // kept set IS these 15 values
            for (int k = 0; k < TOPK; k++) S += expf(top[k] - lmax);
            g_lmax = lmax; g_pivot = top[TOPK - 1]; g_S = S;
        }
    }
}

// KDE (125 blocks): vectorized argmax(probs/noise); zeroes its own bitmap
// words (self-clean); LAST block writes the sample and resets amax/counter.
__global__ void __launch_bounds__(NTHR, 1)
kDE_argmax(const float* __restrict__ logits, const float* __restrict__ noise,
           float* __restrict__ out, int out_size) {
    __shared__ unsigned long long red[NWARP];
    __shared__ int s_last;
    int tid = threadIdx.x, lane = tid & 31, w = tid >> 5;
    const float piv = g_pivot, lmax = g_lmax, S = g_S;

    int base = (blockIdx.x * NTHR + tid) * 4;
    float4 l = plog4(*(const float4*)(logits + base), base);
    float4 nz = *(const float4*)(noise + base);

    // kept: (exp(l-lmax)/S)/noise ; masked: 0/noise (exact +-0 / NaN like ref).
    // +-0 unify to ONE key (first-index ties, IEEE +0==-0 under jnp.argmax);
    // NaN keys order above everything (NaN propagation).
    auto key_of = [&](float lv, float nv, int i) -> unsigned long long {
        float v = (lv >= piv) ? __fdiv_rn(__fdiv_rn(expf(lv - lmax), S), nv)
                              : __fdiv_rn(0.0f, nv);
        unsigned ov = (v == 0.0f) ? 0x80000000u : ordered(v);
        return ((unsigned long long)ov << 32)
             | (unsigned long long)(0xFFFFFFFFu - (unsigned)i);
    };
    unsigned long long b = key_of(l.x, nz.x, base + 0);
    unsigned long long t1 = key_of(l.y, nz.y, base + 1); if (t1 > b) b = t1;
    unsigned long long t2 = key_of(l.z, nz.z, base + 2); if (t2 > b) b = t2;
    unsigned long long t3 = key_of(l.w, nz.w, base + 3); if (t3 > b) b = t3;

    b = warp_max(b);
    if (lane == 0) red[w] = b;
    __syncthreads();                              // all bitmap reads done
    if ((tid & 7) == 0) g_bitmap[base >> 5] = 0u; // self-clean own 32 words
    if (w == 0) {
        unsigned long long m = (lane < NWARP) ? red[lane] : NEG_KEY;
        m = warp_max(m);
        if (lane == 0) atomicMax(&g_amax, m);
    }
    __syncthreads();
    if (tid == 0) {
        __threadfence();
        unsigned c = atomicAdd(&g_ctrD, 1u);
        s_last = (c == gridDim.x - 1);
        if (s_last) g_ctrD = 0u;                  // self-clean
    }
    __syncthreads();
    if (!s_last) return;
    if (tid == 0) {
        unsigned long long m = atomicAdd(&g_amax, 0ull);   // coherent L2 read
        g_amax = 0ull;                            // self-clean
        float fidx = (float)(int)(0xFFFFFFFFu - (unsigned)(m & 0xFFFFFFFFull));
        out[0] = fidx;                                     // samples
        if (out_size >= HISTLEN + 2) out[1 + HISTLEN] = fidx;  // y_new tail
        for (int j = HISTLEN + 2; j < out_size; j++) out[j] = fidx;
    }
}

extern "C" void kernel_launch(void* const* d_in, const int* in_sizes, int n_in,
                              void* d_out, int out_size) {
    // y = the size-2048 tensor; among the remaining two (metadata order),
    // logits precedes noise (validated rounds 9-11).
    int iy = 1;
    for (int i = 0; i < n_in; i++) if (in_sizes[i] == HISTLEN) { iy = i; break; }
    int fl[2]; int nf = 0;
    for (int i = 0; i < n_in && nf < 2; i++) if (i != iy) fl[nf++] = i;

    const float* logits = (const float*)d_in[fl[0]];
    const float* noise  = (const float*)d_in[fl[1]];
    const int*   y      = (const int*)d_in[iy];
    float* out = (float*)d_out;

    kA_prep   <<<HISTLEN / NTHR, NTHR>>>(y, out, out_size);   // 8 blocks
    kBC_top   <<<NBLK, NTHR>>>(logits);
    kDE_argmax<<<NBLK, NTHR>>>(logits, noise, out, out_size);
}